// round 2
// baseline (speedup 1.0000x reference)
#include <cuda_runtime.h>
#include <math.h>

#define B_  4
#define N_  8192
#define M_  8192
#define FEAT 64
#define KNN_K 16
#define K4  4
#define TILE 2048
#define KNN_THREADS 64
#define S2_THREADS 128
#define S2_WARPS 4
#define FULLMASK 0xffffffffu

// Scratch: knn indices (B, N, K) — static device global (no allocation).
__device__ int g_knn_idx[B_ * N_ * KNN_K];

// ---------------------------------------------------------------------------
// Kernel 1: fused distance scan + exact top-16 selection.
// Distance arithmetic emulates the XLA reference bit-exactly:
//   q2/o2 : plain-rounded ((x*x + y*y) + z*z)      (no fma)
//   cross : forward fma chain fma(z,oz, fma(y,oy, rn(x*ox)))  (Eigen gebp)
//   d2    : fsub(fadd(q2, o2), fmul(2, cross))
// Thread-per-query; warp lanes share the same point m (smem broadcast reads).
// Per-lane sorted insertion list (strict '<' => stable ties, matches top_k).
// ---------------------------------------------------------------------------
__global__ void __launch_bounds__(KNN_THREADS) knn_kernel(
    const float* __restrict__ orig, const float* __restrict__ query)
{
    __shared__ float sx[TILE], sy[TILE], sz[TILE], so[TILE];

    const int b = blockIdx.y;
    const int q = blockIdx.x * KNN_THREADS + threadIdx.x;

    const float* __restrict__ ox = orig + (size_t)b * 3 * M_;
    const float* __restrict__ oy = ox + M_;
    const float* __restrict__ oz = ox + 2 * M_;

    const float qx = query[(b * 3 + 0) * N_ + q];
    const float qy = query[(b * 3 + 1) * N_ + q];
    const float qz = query[(b * 3 + 2) * N_ + q];
    // q2 = ((qx^2 + qy^2) + qz^2), every op individually rounded, no fma
    const float q2 = __fadd_rn(__fadd_rn(__fmul_rn(qx, qx), __fmul_rn(qy, qy)),
                               __fmul_rn(qz, qz));

    float dl[KNN_K];
    int   il[KNN_K];
    const float INF = __int_as_float(0x7f800000);
#pragma unroll
    for (int j = 0; j < KNN_K; ++j) { dl[j] = INF; il[j] = 0; }

    for (int t = 0; t < M_; t += TILE) {
        __syncthreads();
        for (int i = threadIdx.x; i < TILE; i += KNN_THREADS) {
            float x = ox[t + i];
            float y = oy[t + i];
            float z = oz[t + i];
            sx[i] = x; sy[i] = y; sz[i] = z;
            // o2 with plain rounding, no fma (matches XLA fused reduce)
            so[i] = __fadd_rn(__fadd_rn(__fmul_rn(x, x), __fmul_rn(y, y)),
                              __fmul_rn(z, z));
        }
        __syncthreads();

#pragma unroll 4
        for (int m = 0; m < TILE; ++m) {
            // Eigen gebp K=3 forward fma chain: fma(a0,b0,0)=rn(a0*b0)
            float c = __fmul_rn(qx, sx[m]);
            c = fmaf(qy, sy[m], c);
            c = fmaf(qz, sz[m], c);
            // d2 = (q2 + o2) - 2*cross, each step rounded
            float d = __fsub_rn(__fadd_rn(q2, so[m]), __fmul_rn(2.0f, c));
            if (d < dl[KNN_K - 1]) {
                dl[KNN_K - 1] = d;
                il[KNN_K - 1] = t + m;
                // bubble up (stable: strict '<' keeps equal after existing)
#pragma unroll
                for (int j = KNN_K - 1; j > 0; --j) {
                    bool sw = dl[j] < dl[j - 1];
                    float flo = sw ? dl[j]     : dl[j - 1];
                    float fhi = sw ? dl[j - 1] : dl[j];
                    int   ilo = sw ? il[j]     : il[j - 1];
                    int   ihi = sw ? il[j - 1] : il[j];
                    dl[j - 1] = flo; dl[j] = fhi;
                    il[j - 1] = ilo; il[j] = ihi;
                }
            }
        }
    }

    int* outp = g_knn_idx + ((size_t)b * N_ + q) * KNN_K;
#pragma unroll
    for (int j = 0; j < KNN_K; ++j) outp[j] = il[j];
}

// ---------------------------------------------------------------------------
// Kernel 2: fused MLP0 (3->64) + max-pool + MLP1 (64->64, only k<4) +
// sigmoid gate + gather + weighted sum. Warp-per-query, BN folded into conv.
// ---------------------------------------------------------------------------
__global__ void __launch_bounds__(S2_THREADS) fuse_kernel(
    const float* __restrict__ orig, const float* __restrict__ query,
    const float* __restrict__ local_feat,
    const float* __restrict__ w0, const float* __restrict__ b0,
    const float* __restrict__ g0, const float* __restrict__ be0,
    const float* __restrict__ m0, const float* __restrict__ v0,
    const float* __restrict__ w1, const float* __restrict__ b1,
    const float* __restrict__ g1, const float* __restrict__ be1,
    const float* __restrict__ m1, const float* __restrict__ v1,
    const float* __restrict__ w2, const float* __restrict__ b2,
    float* __restrict__ out)
{
    __shared__ float sW0[3][FEAT];
    __shared__ float sB0[FEAT];
    __shared__ float sW1[FEAT][FEAT + 1];   // +1 pad: conflict-free row reads
    __shared__ float sB1[FEAT];
    __shared__ float sW2[2 * FEAT];
    __shared__ float sS1[FEAT];
    __shared__ float sF0[S2_WARPS][K4][FEAT];

    const int tid = threadIdx.x;

    if (tid < FEAT) {
        float s0 = g0[tid] / sqrtf(v0[tid] + 1e-5f);
        sB0[tid] = (b0[tid] - m0[tid]) * s0 + be0[tid];
        sW0[0][tid] = w0[tid * 3 + 0] * s0;
        sW0[1][tid] = w0[tid * 3 + 1] * s0;
        sW0[2][tid] = w0[tid * 3 + 2] * s0;
        float s1 = g1[tid] / sqrtf(v1[tid] + 1e-5f);
        sS1[tid] = s1;
        sB1[tid] = (b1[tid] - m1[tid]) * s1 + be1[tid];
        sW2[tid] = w2[tid];
        sW2[tid + FEAT] = w2[tid + FEAT];
    }
    __syncthreads();
    for (int i = tid; i < FEAT * FEAT; i += S2_THREADS) {
        int c = i >> 6;
        sW1[c][i & 63] = w1[i] * sS1[c];
    }
    __syncthreads();

    const int warp = tid >> 5;
    const int lane = tid & 31;
    const int qid = blockIdx.x * S2_WARPS + warp;
    const int b = qid >> 13;          // / N_
    const int n = qid & (N_ - 1);

    const int* kp = g_knn_idx + (size_t)qid * KNN_K;
    int kidx = (lane < KNN_K) ? kp[lane] : 0;

    const float qx = query[(b * 3 + 0) * N_ + n];
    const float qy = query[(b * 3 + 1) * N_ + n];
    const float qz = query[(b * 3 + 2) * N_ + n];

    // prefetch neighbor coords (lanes 0..15 own one neighbor each)
    float px = 0.f, py = 0.f, pz = 0.f;
    {
        const float* ob = orig + (size_t)b * 3 * M_;
        if (lane < KNN_K) {
            px = ob[kidx];
            py = ob[M_ + kidx];
            pz = ob[2 * M_ + kidx];
        }
    }

    const int c0 = lane, c1 = lane + 32;
    const float w0x0 = sW0[0][c0], w0y0 = sW0[1][c0], w0z0 = sW0[2][c0], bb00 = sB0[c0];
    const float w0x1 = sW0[0][c1], w0y1 = sW0[1][c1], w0z1 = sW0[2][c1], bb01 = sB0[c1];

    float fg0 = 0.f, fg1 = 0.f;   // relu outputs are >= 0, so 0 init == max

#pragma unroll
    for (int k = 0; k < KNN_K; ++k) {
        float rx = __shfl_sync(FULLMASK, px, k) - qx;
        float ry = __shfl_sync(FULLMASK, py, k) - qy;
        float rz = __shfl_sync(FULLMASK, pz, k) - qz;
        float a0 = fmaf(w0x0, rx, fmaf(w0y0, ry, fmaf(w0z0, rz, bb00)));
        float a1 = fmaf(w0x1, rx, fmaf(w0y1, ry, fmaf(w0z1, rz, bb01)));
        a0 = fmaxf(a0, 0.f);
        a1 = fmaxf(a1, 0.f);
        fg0 = fmaxf(fg0, a0);
        fg1 = fmaxf(fg1, a1);
        if (k < K4) {
            sF0[warp][k][c0] = a0;
            sF0[warp][k][c1] = a1;
        }
    }
    __syncwarp();

    float rf0[K4], rf1[K4];
    const float bb10 = sB1[c0], bb11 = sB1[c1];
#pragma unroll
    for (int k = 0; k < K4; ++k) {
        float acc0 = bb10, acc1 = bb11;
#pragma unroll
        for (int cp = 0; cp < FEAT; ++cp) {
            float f = sF0[warp][k][cp];          // broadcast
            acc0 = fmaf(sW1[c0][cp], f, acc0);
            acc1 = fmaf(sW1[c1][cp], f, acc1);
        }
        rf0[k] = fmaxf(acc0, 0.f);
        rf1[k] = fmaxf(acc1, 0.f);
    }

    const float w2a = sW2[c0], w2b = sW2[c1];
    const float w2ga = sW2[FEAT + c0], w2gb = sW2[FEAT + c1];
    const float bias2 = b2[0];
    const float* lf = local_feat + (size_t)b * FEAT * M_;

    float o0 = 0.f, o1 = 0.f;
#pragma unroll
    for (int k = 0; k < K4; ++k) {
        float part = w2a * rf0[k] + w2b * rf1[k] + w2ga * fg0 + w2gb * fg1;
#pragma unroll
        for (int s = 16; s > 0; s >>= 1)
            part += __shfl_xor_sync(FULLMASK, part, s);
        float wk = 1.0f / (1.0f + expf(-(part + bias2)));
        int mk = __shfl_sync(FULLMASK, kidx, k);
        float pf0 = lf[(size_t)c0 * M_ + mk];
        float pf1 = lf[(size_t)c1 * M_ + mk];
        o0 += (1.0f - wk) * rf0[k] + wk * pf0;
        o1 += (1.0f - wk) * rf1[k] + wk * pf1;
    }

    out[((size_t)b * FEAT + c0) * N_ + n] = o0;
    out[((size_t)b * FEAT + c1) * N_ + n] = o1;
}

// ---------------------------------------------------------------------------
extern "C" void kernel_launch(void* const* d_in, const int* in_sizes, int n_in,
                              void* d_out, int out_size)
{
    (void)in_sizes; (void)n_in; (void)out_size;
    const float* orig  = (const float*)d_in[0];
    const float* query = (const float*)d_in[1];
    const float* lf    = (const float*)d_in[2];
    const float* w0 = (const float*)d_in[3];
    const float* b0 = (const float*)d_in[4];
    const float* g0 = (const float*)d_in[5];
    const float* be0 = (const float*)d_in[6];
    const float* m0 = (const float*)d_in[7];
    const float* v0 = (const float*)d_in[8];
    const float* w1 = (const float*)d_in[9];
    const float* b1 = (const float*)d_in[10];
    const float* g1 = (const float*)d_in[11];
    const float* be1 = (const float*)d_in[12];
    const float* m1 = (const float*)d_in[13];
    const float* v1 = (const float*)d_in[14];
    const float* w2 = (const float*)d_in[15];
    const float* b2 = (const float*)d_in[16];
    float* out = (float*)d_out;

    dim3 gknn(N_ / KNN_THREADS, B_);
    knn_kernel<<<gknn, KNN_THREADS>>>(orig, query);

    fuse_kernel<<<(B_ * N_) / S2_WARPS, S2_THREADS>>>(
        orig, query, lf,
        w0, b0, g0, be0, m0, v0,
        w1, b1, g1, be1, m1, v1,
        w2, b2, out);
}

// round 3
// speedup vs baseline: 1.5576x; 1.5576x over previous
#include <cuda_runtime.h>
#include <math.h>

#define B_  4
#define N_  8192
#define M_  8192
#define FEAT 64
#define KNN_K 16
#define K4  4
#define S_  4
#define SPLIT_M (M_ / S_)          // 2048
#define P1_THREADS 128
#define BUF 16
#define S2_THREADS 256
#define S2_WARPS 8
#define FULLMASK 0xffffffffu

// Static device scratch (no allocation allowed).
__device__ int   g_knn_idx[B_ * N_ * KNN_K];
__device__ float g_cand_d[S_][KNN_K][B_ * N_];
__device__ int   g_cand_i[S_][KNN_K][B_ * N_];

// ---------------------------------------------------------------------------
// Phase 1: per-split distance scan + buffered exact top-16.
// Distance bits match XLA reference exactly:
//   q2/o2: plain-rounded ((x*x + y*y) + z*z), no fma
//   cross: forward fma chain fma(z,oz, fma(y,oy, rn(x*ox)))
//   d2   : fmaf(-2, c, fadd(q2,o2))  ==  fsub(fadd(q2,o2), fmul(2,c))
//          (bit-identical: multiply by 2 is exact)
// Hot loop: 1 LDS.128 + 6 FP + SETP + rare predicated append. Insertion-sort
// work is batched into flushes so all 32 lanes insert in parallel.
// ---------------------------------------------------------------------------
__global__ void __launch_bounds__(P1_THREADS) knn_part_kernel(
    const float* __restrict__ orig, const float* __restrict__ query)
{
    __shared__ float4 tile[SPLIT_M];
    __shared__ float  bufD[BUF][P1_THREADS];
    __shared__ int    bufI[BUF][P1_THREADS];

    const int b = blockIdx.y;
    const int s = blockIdx.z;
    const int tid = threadIdx.x;
    const int q = blockIdx.x * P1_THREADS + tid;
    const int mbase = s * SPLIT_M;

    const float* __restrict__ ox = orig + (size_t)b * 3 * M_;
    const float* __restrict__ oy = ox + M_;
    const float* __restrict__ oz = ox + 2 * M_;

    for (int i = tid; i < SPLIT_M; i += P1_THREADS) {
        float x = ox[mbase + i];
        float y = oy[mbase + i];
        float z = oz[mbase + i];
        float o2 = __fadd_rn(__fadd_rn(__fmul_rn(x, x), __fmul_rn(y, y)),
                             __fmul_rn(z, z));
        tile[i] = make_float4(x, y, z, o2);
    }

    const float qx = query[(b * 3 + 0) * N_ + q];
    const float qy = query[(b * 3 + 1) * N_ + q];
    const float qz = query[(b * 3 + 2) * N_ + q];
    const float q2 = __fadd_rn(__fadd_rn(__fmul_rn(qx, qx), __fmul_rn(qy, qy)),
                               __fmul_rn(qz, qz));

    float dl[KNN_K];
    int   il[KNN_K];
    const float INF = __int_as_float(0x7f800000);
#pragma unroll
    for (int j = 0; j < KNN_K; ++j) { dl[j] = INF; il[j] = 0; }

    __syncthreads();

    int c = 0;
    for (int m0 = 0; m0 < SPLIT_M; m0 += 8) {
#pragma unroll
        for (int u = 0; u < 8; ++u) {
            float4 p = tile[m0 + u];
            float cr = __fmul_rn(qx, p.x);
            cr = fmaf(qy, p.y, cr);
            cr = fmaf(qz, p.z, cr);
            float ssum = __fadd_rn(q2, p.w);
            float d = fmaf(-2.0f, cr, ssum);
            if (d < dl[KNN_K - 1]) {
                bufD[c][tid] = d;
                bufI[c][tid] = mbase + m0 + u;
                ++c;
            }
        }
        if (__any_sync(FULLMASK, c > 8)) {
            // FIFO drain preserves ascending-index order among equal dists
            for (int j = 0; j < c; ++j) {
                float d = bufD[j][tid];
                int   i = bufI[j][tid];
                if (d < dl[KNN_K - 1]) {
                    dl[KNN_K - 1] = d;
                    il[KNN_K - 1] = i;
#pragma unroll
                    for (int t = KNN_K - 1; t > 0; --t) {
                        bool sw = dl[t] < dl[t - 1];
                        float flo = sw ? dl[t]     : dl[t - 1];
                        float fhi = sw ? dl[t - 1] : dl[t];
                        int   ilo = sw ? il[t]     : il[t - 1];
                        int   ihi = sw ? il[t - 1] : il[t];
                        dl[t - 1] = flo; dl[t] = fhi;
                        il[t - 1] = ilo; il[t] = ihi;
                    }
                }
            }
            c = 0;
        }
    }
    // tail flush
    for (int j = 0; j < c; ++j) {
        float d = bufD[j][tid];
        int   i = bufI[j][tid];
        if (d < dl[KNN_K - 1]) {
            dl[KNN_K - 1] = d;
            il[KNN_K - 1] = i;
#pragma unroll
            for (int t = KNN_K - 1; t > 0; --t) {
                bool sw = dl[t] < dl[t - 1];
                float flo = sw ? dl[t]     : dl[t - 1];
                float fhi = sw ? dl[t - 1] : dl[t];
                int   ilo = sw ? il[t]     : il[t - 1];
                int   ihi = sw ? il[t - 1] : il[t];
                dl[t - 1] = flo; dl[t] = fhi;
                il[t - 1] = ilo; il[t] = ihi;
            }
        }
    }

    const int gq = b * N_ + q;
#pragma unroll
    for (int j = 0; j < KNN_K; ++j) {
        g_cand_d[s][j][gq] = dl[j];
        g_cand_i[s][j][gq] = il[j];
    }
}

// ---------------------------------------------------------------------------
// Phase 2: stable 4-way merge of per-split sorted top-16 lists.
// Lexicographic (d, idx) == jax.lax.top_k tie-breaking (lowest index first).
// ---------------------------------------------------------------------------
__global__ void __launch_bounds__(128) knn_merge_kernel()
{
    const int q = blockIdx.x * 128 + threadIdx.x;   // global query id
    const float INF = __int_as_float(0x7f800000);

    float hd0 = g_cand_d[0][0][q], hd1 = g_cand_d[1][0][q];
    float hd2 = g_cand_d[2][0][q], hd3 = g_cand_d[3][0][q];
    int   hi0 = g_cand_i[0][0][q], hi1 = g_cand_i[1][0][q];
    int   hi2 = g_cand_i[2][0][q], hi3 = g_cand_i[3][0][q];
    int p0 = 0, p1 = 0, p2 = 0, p3 = 0;

    int* outp = g_knn_idx + (size_t)q * KNN_K;

#pragma unroll
    for (int step = 0; step < KNN_K; ++step) {
        bool a01 = (hd0 < hd1) || (hd0 == hd1 && hi0 < hi1);
        float dA = a01 ? hd0 : hd1;  int iA = a01 ? hi0 : hi1;
        bool a23 = (hd2 < hd3) || (hd2 == hd3 && hi2 < hi3);
        float dB = a23 ? hd2 : hd3;  int iB = a23 ? hi2 : hi3;
        bool aAB = (dA < dB) || (dA == dB && iA < iB);
        outp[step] = aAB ? iA : iB;
        if (aAB) {
            if (a01) {
                ++p0;
                if (p0 < KNN_K) { hd0 = g_cand_d[0][p0][q]; hi0 = g_cand_i[0][p0][q]; }
                else            { hd0 = INF; hi0 = 0x7fffffff; }
            } else {
                ++p1;
                if (p1 < KNN_K) { hd1 = g_cand_d[1][p1][q]; hi1 = g_cand_i[1][p1][q]; }
                else            { hd1 = INF; hi1 = 0x7fffffff; }
            }
        } else {
            if (a23) {
                ++p2;
                if (p2 < KNN_K) { hd2 = g_cand_d[2][p2][q]; hi2 = g_cand_i[2][p2][q]; }
                else            { hd2 = INF; hi2 = 0x7fffffff; }
            } else {
                ++p3;
                if (p3 < KNN_K) { hd3 = g_cand_d[3][p3][q]; hi3 = g_cand_i[3][p3][q]; }
                else            { hd3 = INF; hi3 = 0x7fffffff; }
            }
        }
    }
}

// ---------------------------------------------------------------------------
// Phase 3: fused MLP0 (3->64) + max-pool + MLP1 (64->64, k<4) + sigmoid gate
// + gather + weighted sum. Warp-per-query, BN folded. 8 warps/block.
// ---------------------------------------------------------------------------
__global__ void __launch_bounds__(S2_THREADS) fuse_kernel(
    const float* __restrict__ orig, const float* __restrict__ query,
    const float* __restrict__ local_feat,
    const float* __restrict__ w0, const float* __restrict__ b0,
    const float* __restrict__ g0, const float* __restrict__ be0,
    const float* __restrict__ m0, const float* __restrict__ v0,
    const float* __restrict__ w1, const float* __restrict__ b1,
    const float* __restrict__ g1, const float* __restrict__ be1,
    const float* __restrict__ m1, const float* __restrict__ v1,
    const float* __restrict__ w2, const float* __restrict__ b2,
    float* __restrict__ out)
{
    __shared__ float sW0[3][FEAT];
    __shared__ float sB0[FEAT];
    __shared__ float sW1[FEAT][FEAT + 1];   // +1 pad: conflict-free row reads
    __shared__ float sB1[FEAT];
    __shared__ float sW2[2 * FEAT];
    __shared__ float sS1[FEAT];
    __shared__ float sF0[S2_WARPS][FEAT][K4];  // [cp][k] -> float4 broadcast read

    const int tid = threadIdx.x;

    if (tid < FEAT) {
        float s0 = g0[tid] / sqrtf(v0[tid] + 1e-5f);
        sB0[tid] = (b0[tid] - m0[tid]) * s0 + be0[tid];
        sW0[0][tid] = w0[tid * 3 + 0] * s0;
        sW0[1][tid] = w0[tid * 3 + 1] * s0;
        sW0[2][tid] = w0[tid * 3 + 2] * s0;
        float s1 = g1[tid] / sqrtf(v1[tid] + 1e-5f);
        sS1[tid] = s1;
        sB1[tid] = (b1[tid] - m1[tid]) * s1 + be1[tid];
        sW2[tid] = w2[tid];
        sW2[tid + FEAT] = w2[tid + FEAT];
    }
    __syncthreads();
    for (int i = tid; i < FEAT * FEAT; i += S2_THREADS) {
        int ch = i >> 6;
        sW1[ch][i & 63] = w1[i] * sS1[ch];
    }
    __syncthreads();

    const int warp = tid >> 5;
    const int lane = tid & 31;
    const int qid = blockIdx.x * S2_WARPS + warp;
    const int b = qid >> 13;          // / N_
    const int n = qid & (N_ - 1);

    const int* kp = g_knn_idx + (size_t)qid * KNN_K;
    int kidx = (lane < KNN_K) ? kp[lane] : 0;

    const float qx = query[(b * 3 + 0) * N_ + n];
    const float qy = query[(b * 3 + 1) * N_ + n];
    const float qz = query[(b * 3 + 2) * N_ + n];

    float px = 0.f, py = 0.f, pz = 0.f;
    {
        const float* ob = orig + (size_t)b * 3 * M_;
        if (lane < KNN_K) {
            px = ob[kidx];
            py = ob[M_ + kidx];
            pz = ob[2 * M_ + kidx];
        }
    }

    const int c0 = lane, c1 = lane + 32;
    const float w0x0 = sW0[0][c0], w0y0 = sW0[1][c0], w0z0 = sW0[2][c0], bb00 = sB0[c0];
    const float w0x1 = sW0[0][c1], w0y1 = sW0[1][c1], w0z1 = sW0[2][c1], bb01 = sB0[c1];

    float fg0 = 0.f, fg1 = 0.f;   // relu >= 0 so 0 init == max

#pragma unroll
    for (int k = 0; k < KNN_K; ++k) {
        float rx = __shfl_sync(FULLMASK, px, k) - qx;
        float ry = __shfl_sync(FULLMASK, py, k) - qy;
        float rz = __shfl_sync(FULLMASK, pz, k) - qz;
        float a0 = fmaf(w0x0, rx, fmaf(w0y0, ry, fmaf(w0z0, rz, bb00)));
        float a1 = fmaf(w0x1, rx, fmaf(w0y1, ry, fmaf(w0z1, rz, bb01)));
        a0 = fmaxf(a0, 0.f);
        a1 = fmaxf(a1, 0.f);
        fg0 = fmaxf(fg0, a0);
        fg1 = fmaxf(fg1, a1);
        if (k < K4) {
            sF0[warp][c0][k] = a0;
            sF0[warp][c1][k] = a1;
        }
    }
    __syncwarp();

    const float bb10 = sB1[c0], bb11 = sB1[c1];
    float ra0 = bb10, ra1 = bb10, ra2 = bb10, ra3 = bb10;
    float rb0 = bb11, rb1 = bb11, rb2 = bb11, rb3 = bb11;
#pragma unroll
    for (int cp = 0; cp < FEAT; ++cp) {
        float wa = sW1[c0][cp];
        float wb = sW1[c1][cp];
        float4 f = *reinterpret_cast<const float4*>(&sF0[warp][cp][0]); // broadcast
        ra0 = fmaf(wa, f.x, ra0); ra1 = fmaf(wa, f.y, ra1);
        ra2 = fmaf(wa, f.z, ra2); ra3 = fmaf(wa, f.w, ra3);
        rb0 = fmaf(wb, f.x, rb0); rb1 = fmaf(wb, f.y, rb1);
        rb2 = fmaf(wb, f.z, rb2); rb3 = fmaf(wb, f.w, rb3);
    }
    float rf0[K4], rf1[K4];
    rf0[0] = fmaxf(ra0, 0.f); rf0[1] = fmaxf(ra1, 0.f);
    rf0[2] = fmaxf(ra2, 0.f); rf0[3] = fmaxf(ra3, 0.f);
    rf1[0] = fmaxf(rb0, 0.f); rf1[1] = fmaxf(rb1, 0.f);
    rf1[2] = fmaxf(rb2, 0.f); rf1[3] = fmaxf(rb3, 0.f);

    const float w2a = sW2[c0], w2b = sW2[c1];
    const float w2ga = sW2[FEAT + c0], w2gb = sW2[FEAT + c1];
    const float bias2 = b2[0];
    const float* lf = local_feat + (size_t)b * FEAT * M_;

    float o0 = 0.f, o1 = 0.f;
#pragma unroll
    for (int k = 0; k < K4; ++k) {
        float part = w2a * rf0[k] + w2b * rf1[k] + w2ga * fg0 + w2gb * fg1;
#pragma unroll
        for (int sdown = 16; sdown > 0; sdown >>= 1)
            part += __shfl_xor_sync(FULLMASK, part, sdown);
        float wk = 1.0f / (1.0f + expf(-(part + bias2)));
        int mk = __shfl_sync(FULLMASK, kidx, k);
        float pf0 = lf[(size_t)c0 * M_ + mk];
        float pf1 = lf[(size_t)c1 * M_ + mk];
        o0 += (1.0f - wk) * rf0[k] + wk * pf0;
        o1 += (1.0f - wk) * rf1[k] + wk * pf1;
    }

    out[((size_t)b * FEAT + c0) * N_ + n] = o0;
    out[((size_t)b * FEAT + c1) * N_ + n] = o1;
}

// ---------------------------------------------------------------------------
extern "C" void kernel_launch(void* const* d_in, const int* in_sizes, int n_in,
                              void* d_out, int out_size)
{
    (void)in_sizes; (void)n_in; (void)out_size;
    const float* orig  = (const float*)d_in[0];
    const float* query = (const float*)d_in[1];
    const float* lf    = (const float*)d_in[2];
    const float* w0 = (const float*)d_in[3];
    const float* b0 = (const float*)d_in[4];
    const float* g0 = (const float*)d_in[5];
    const float* be0 = (const float*)d_in[6];
    const float* m0 = (const float*)d_in[7];
    const float* v0 = (const float*)d_in[8];
    const float* w1 = (const float*)d_in[9];
    const float* b1 = (const float*)d_in[10];
    const float* g1 = (const float*)d_in[11];
    const float* be1 = (const float*)d_in[12];
    const float* m1 = (const float*)d_in[13];
    const float* v1 = (const float*)d_in[14];
    const float* w2 = (const float*)d_in[15];
    const float* b2 = (const float*)d_in[16];
    float* out = (float*)d_out;

    dim3 g1d(N_ / P1_THREADS, B_, S_);
    knn_part_kernel<<<g1d, P1_THREADS>>>(orig, query);

    knn_merge_kernel<<<(B_ * N_) / 128, 128>>>();

    fuse_kernel<<<(B_ * N_) / S2_WARPS, S2_THREADS>>>(
        orig, query, lf,
        w0, b0, g0, be0, m0, v0,
        w1, b1, g1, be1, m1, v1,
        w2, b2, out);
}

// round 7
// speedup vs baseline: 1.7292x; 1.1102x over previous
#include <cuda_runtime.h>
#include <math.h>

#define B_  4
#define N_  8192
#define M_  8192
#define FEAT 64
#define KNN_K 16
#define K4  4
#define S_  4
#define SPLIT_M (M_ / S_)          // 2048
#define TILE1 1024
#define P1_THREADS 128
#define BUF 15
#define S2_THREADS 256
#define S2_WARPS 8
#define FULLMASK 0xffffffffu

// Static device scratch (no allocation allowed).
__device__ int   g_knn_idx[B_ * N_ * KNN_K];
__device__ float g_cand_d[S_][KNN_K][B_ * N_];
__device__ int   g_cand_i[S_][KNN_K][B_ * N_];

// ---------------------------------------------------------------------------
// Phase 1: per-split distance scan + buffered exact top-16.
// Distance bits match XLA reference exactly:
//   q2/o2: plain-rounded ((x*x + y*y) + z*z), no fma
//   cross: forward fma chain fma(z,oz, fma(y,oy, rn(x*ox)))
//   d2   : fmaf(-2, c, fadd(q2,o2))  ==  fsub(fadd(q2,o2), fmul(2,c))
// Hot loop: 1 LDS.128 (broadcast) + 5 FP + SETP + rare predicated append via
// running byte-offset (bases fold into STS immediates). Insertion sorting is
// batched into flushes where all 32 lanes insert in parallel.
// smem = 16KB tile + 15KB buffer -> 7 blocks/SM (vs 4 before).
// ---------------------------------------------------------------------------
__global__ void __launch_bounds__(P1_THREADS, 7) knn_part_kernel(
    const float* __restrict__ orig, const float* __restrict__ query)
{
    __shared__ float4 tile[TILE1];                 // 16 KB
    __shared__ float  bufD[BUF][P1_THREADS];       // 7.5 KB
    __shared__ int    bufI[BUF][P1_THREADS];       // 7.5 KB

    const int b = blockIdx.y;
    const int s = blockIdx.z;
    const int tid = threadIdx.x;
    const int q = blockIdx.x * P1_THREADS + tid;
    const int mbase = s * SPLIT_M;

    const float* __restrict__ ox = orig + (size_t)b * 3 * M_;
    const float* __restrict__ oy = ox + M_;
    const float* __restrict__ oz = ox + 2 * M_;

    const float qx = query[(b * 3 + 0) * N_ + q];
    const float qy = query[(b * 3 + 1) * N_ + q];
    const float qz = query[(b * 3 + 2) * N_ + q];
    const float q2 = __fadd_rn(__fadd_rn(__fmul_rn(qx, qx), __fmul_rn(qy, qy)),
                               __fmul_rn(qz, qz));

    float dl[KNN_K];
    int   il[KNN_K];
    const float INF = __int_as_float(0x7f800000);
#pragma unroll
    for (int j = 0; j < KNN_K; ++j) { dl[j] = INF; il[j] = 0; }

    // running byte offsets into bufD / bufI (row stride = P1_THREADS*4 bytes)
    char* const bD0 = (char*)&bufD[0][0] + tid * 4;
    char* const bI0 = (char*)&bufI[0][0] + tid * 4;
    int off = 0;                                   // bytes; slot = off / 512
    const int offFlushLim = 7 * (P1_THREADS * 4);  // flush when off > this

    for (int tb = 0; tb < SPLIT_M; tb += TILE1) {
        __syncthreads();
        for (int i = tid; i < TILE1; i += P1_THREADS) {
            float x = ox[mbase + tb + i];
            float y = oy[mbase + tb + i];
            float z = oz[mbase + tb + i];
            float o2 = __fadd_rn(__fadd_rn(__fmul_rn(x, x), __fmul_rn(y, y)),
                                 __fmul_rn(z, z));
            tile[i] = make_float4(x, y, z, o2);
        }
        __syncthreads();

        for (int m0 = 0; m0 < TILE1; m0 += 8) {
#pragma unroll
            for (int u = 0; u < 8; ++u) {
                float4 p = tile[m0 + u];
                float cr = __fmul_rn(qx, p.x);
                cr = fmaf(qy, p.y, cr);
                cr = fmaf(qz, p.z, cr);
                float ssum = __fadd_rn(q2, p.w);
                float d = fmaf(-2.0f, cr, ssum);
                if (d < dl[KNN_K - 1]) {
                    *(float*)(bD0 + off) = d;
                    *(int*)(bI0 + off) = mbase + tb + m0 + u;
                    off += P1_THREADS * 4;
                }
            }
            if (__any_sync(FULLMASK, off > offFlushLim)) {
                const int c = off / (P1_THREADS * 4);
                for (int j = 0; j < c; ++j) {
                    float d = bufD[j][tid];
                    int   i = bufI[j][tid];
                    if (d < dl[KNN_K - 1]) {
                        dl[KNN_K - 1] = d;
                        il[KNN_K - 1] = i;
#pragma unroll
                        for (int t = KNN_K - 1; t > 0; --t) {
                            bool sw = dl[t] < dl[t - 1];
                            float flo = sw ? dl[t]     : dl[t - 1];
                            float fhi = sw ? dl[t - 1] : dl[t];
                            int   ilo = sw ? il[t]     : il[t - 1];
                            int   ihi = sw ? il[t - 1] : il[t];
                            dl[t - 1] = flo; dl[t] = fhi;
                            il[t - 1] = ilo; il[t] = ihi;
                        }
                    }
                }
                off = 0;
            }
        }
    }
    // tail flush
    {
        const int c = off / (P1_THREADS * 4);
        for (int j = 0; j < c; ++j) {
            float d = bufD[j][tid];
            int   i = bufI[j][tid];
            if (d < dl[KNN_K - 1]) {
                dl[KNN_K - 1] = d;
                il[KNN_K - 1] = i;
#pragma unroll
                for (int t = KNN_K - 1; t > 0; --t) {
                    bool sw = dl[t] < dl[t - 1];
                    float flo = sw ? dl[t]     : dl[t - 1];
                    float fhi = sw ? dl[t - 1] : dl[t];
                    int   ilo = sw ? il[t]     : il[t - 1];
                    int   ihi = sw ? il[t - 1] : il[t];
                    dl[t - 1] = flo; dl[t] = fhi;
                    il[t - 1] = ilo; il[t] = ihi;
                }
            }
        }
    }

    const int gq = b * N_ + q;
#pragma unroll
    for (int j = 0; j < KNN_K; ++j) {
        g_cand_d[s][j][gq] = dl[j];
        g_cand_i[s][j][gq] = il[j];
    }
}

// ---------------------------------------------------------------------------
// Phase 2: stable 4-way merge of per-split sorted top-16 lists.
// Lexicographic (d, idx) == jax.lax.top_k tie-breaking (lowest index first).
// ---------------------------------------------------------------------------
__global__ void __launch_bounds__(128) knn_merge_kernel()
{
    const int q = blockIdx.x * 128 + threadIdx.x;   // global query id
    const float INF = __int_as_float(0x7f800000);

    float hd0 = g_cand_d[0][0][q], hd1 = g_cand_d[1][0][q];
    float hd2 = g_cand_d[2][0][q], hd3 = g_cand_d[3][0][q];
    int   hi0 = g_cand_i[0][0][q], hi1 = g_cand_i[1][0][q];
    int   hi2 = g_cand_i[2][0][q], hi3 = g_cand_i[3][0][q];
    int p0 = 0, p1 = 0, p2 = 0, p3 = 0;

    int* outp = g_knn_idx + (size_t)q * KNN_K;

#pragma unroll
    for (int step = 0; step < KNN_K; ++step) {
        bool a01 = (hd0 < hd1) || (hd0 == hd1 && hi0 < hi1);
        float dA = a01 ? hd0 : hd1;  int iA = a01 ? hi0 : hi1;
        bool a23 = (hd2 < hd3) || (hd2 == hd3 && hi2 < hi3);
        float dB = a23 ? hd2 : hd3;  int iB = a23 ? hi2 : hi3;
        bool aAB = (dA < dB) || (dA == dB && iA < iB);
        outp[step] = aAB ? iA : iB;
        if (aAB) {
            if (a01) {
                ++p0;
                if (p0 < KNN_K) { hd0 = g_cand_d[0][p0][q]; hi0 = g_cand_i[0][p0][q]; }
                else            { hd0 = INF; hi0 = 0x7fffffff; }
            } else {
                ++p1;
                if (p1 < KNN_K) { hd1 = g_cand_d[1][p1][q]; hi1 = g_cand_i[1][p1][q]; }
                else            { hd1 = INF; hi1 = 0x7fffffff; }
            }
        } else {
            if (a23) {
                ++p2;
                if (p2 < KNN_K) { hd2 = g_cand_d[2][p2][q]; hi2 = g_cand_i[2][p2][q]; }
                else            { hd2 = INF; hi2 = 0x7fffffff; }
            } else {
                ++p3;
                if (p3 < KNN_K) { hd3 = g_cand_d[3][p3][q]; hi3 = g_cand_i[3][p3][q]; }
                else            { hd3 = INF; hi3 = 0x7fffffff; }
            }
        }
    }
}

// ---------------------------------------------------------------------------
// Phase 3: fused MLP0 (3->64) + max-pool + MLP1 (64->64, k<4) + sigmoid gate
// + gather + weighted sum. Warp-per-query, BN folded. 8 warps/block.
// ---------------------------------------------------------------------------
__global__ void __launch_bounds__(S2_THREADS) fuse_kernel(
    const float* __restrict__ orig, const float* __restrict__ query,
    const float* __restrict__ local_feat,
    const float* __restrict__ w0, const float* __restrict__ b0,
    const float* __restrict__ g0, const float* __restrict__ be0,
    const float* __restrict__ m0, const float* __restrict__ v0,
    const float* __restrict__ w1, const float* __restrict__ b1,
    const float* __restrict__ g1, const float* __restrict__ be1,
    const float* __restrict__ m1, const float* __restrict__ v1,
    const float* __restrict__ w2, const float* __restrict__ b2,
    float* __restrict__ out)
{
    __shared__ float sW0[3][FEAT];
    __shared__ float sB0[FEAT];
    __shared__ float sW1[FEAT][FEAT + 1];   // +1 pad: conflict-free row reads
    __shared__ float sB1[FEAT];
    __shared__ float sW2[2 * FEAT];
    __shared__ float sS1[FEAT];
    __shared__ float sF0[S2_WARPS][FEAT][K4];  // [cp][k] -> float4 broadcast read

    const int tid = threadIdx.x;

    if (tid < FEAT) {
        float s0 = g0[tid] / sqrtf(v0[tid] + 1e-5f);
        sB0[tid] = (b0[tid] - m0[tid]) * s0 + be0[tid];
        sW0[0][tid] = w0[tid * 3 + 0] * s0;
        sW0[1][tid] = w0[tid * 3 + 1] * s0;
        sW0[2][tid] = w0[tid * 3 + 2] * s0;
        float s1 = g1[tid] / sqrtf(v1[tid] + 1e-5f);
        sS1[tid] = s1;
        sB1[tid] = (b1[tid] - m1[tid]) * s1 + be1[tid];
        sW2[tid] = w2[tid];
        sW2[tid + FEAT] = w2[tid + FEAT];
    }
    __syncthreads();
    for (int i = tid; i < FEAT * FEAT; i += S2_THREADS) {
        int ch = i >> 6;
        sW1[ch][i & 63] = w1[i] * sS1[ch];
    }
    __syncthreads();

    const int warp = tid >> 5;
    const int lane = tid & 31;
    const int qid = blockIdx.x * S2_WARPS + warp;
    const int b = qid >> 13;          // / N_
    const int n = qid & (N_ - 1);

    const int* kp = g_knn_idx + (size_t)qid * KNN_K;
    int kidx = (lane < KNN_K) ? kp[lane] : 0;

    const float qx = query[(b * 3 + 0) * N_ + n];
    const float qy = query[(b * 3 + 1) * N_ + n];
    const float qz = query[(b * 3 + 2) * N_ + n];

    float px = 0.f, py = 0.f, pz = 0.f;
    {
        const float* ob = orig + (size_t)b * 3 * M_;
        if (lane < KNN_K) {
            px = ob[kidx];
            py = ob[M_ + kidx];
            pz = ob[2 * M_ + kidx];
        }
    }

    const int c0 = lane, c1 = lane + 32;
    const float w0x0 = sW0[0][c0], w0y0 = sW0[1][c0], w0z0 = sW0[2][c0], bb00 = sB0[c0];
    const float w0x1 = sW0[0][c1], w0y1 = sW0[1][c1], w0z1 = sW0[2][c1], bb01 = sB0[c1];

    float fg0 = 0.f, fg1 = 0.f;   // relu >= 0 so 0 init == max

#pragma unroll
    for (int k = 0; k < KNN_K; ++k) {
        float rx = __shfl_sync(FULLMASK, px, k) - qx;
        float ry = __shfl_sync(FULLMASK, py, k) - qy;
        float rz = __shfl_sync(FULLMASK, pz, k) - qz;
        float a0 = fmaf(w0x0, rx, fmaf(w0y0, ry, fmaf(w0z0, rz, bb00)));
        float a1 = fmaf(w0x1, rx, fmaf(w0y1, ry, fmaf(w0z1, rz, bb01)));
        a0 = fmaxf(a0, 0.f);
        a1 = fmaxf(a1, 0.f);
        fg0 = fmaxf(fg0, a0);
        fg1 = fmaxf(fg1, a1);
        if (k < K4) {
            sF0[warp][c0][k] = a0;
            sF0[warp][c1][k] = a1;
        }
    }
    __syncwarp();

    const float bb10 = sB1[c0], bb11 = sB1[c1];
    float ra0 = bb10, ra1 = bb10, ra2 = bb10, ra3 = bb10;
    float rb0 = bb11, rb1 = bb11, rb2 = bb11, rb3 = bb11;
#pragma unroll
    for (int cp = 0; cp < FEAT; ++cp) {
        float wa = sW1[c0][cp];
        float wb = sW1[c1][cp];
        float4 f = *reinterpret_cast<const float4*>(&sF0[warp][cp][0]); // broadcast
        ra0 = fmaf(wa, f.x, ra0); ra1 = fmaf(wa, f.y, ra1);
        ra2 = fmaf(wa, f.z, ra2); ra3 = fmaf(wa, f.w, ra3);
        rb0 = fmaf(wb, f.x, rb0); rb1 = fmaf(wb, f.y, rb1);
        rb2 = fmaf(wb, f.z, rb2); rb3 = fmaf(wb, f.w, rb3);
    }
    float rf0[K4], rf1[K4];
    rf0[0] = fmaxf(ra0, 0.f); rf0[1] = fmaxf(ra1, 0.f);
    rf0[2] = fmaxf(ra2, 0.f); rf0[3] = fmaxf(ra3, 0.f);
    rf1[0] = fmaxf(rb0, 0.f); rf1[1] = fmaxf(rb1, 0.f);
    rf1[2] = fmaxf(rb2, 0.f); rf1[3] = fmaxf(rb3, 0.f);

    const float w2a = sW2[c0], w2b = sW2[c1];
    const float w2ga = sW2[FEAT + c0], w2gb = sW2[FEAT + c1];
    const float bias2 = b2[0];
    const float* lf = local_feat + (size_t)b * FEAT * M_;

    float o0 = 0.f, o1 = 0.f;
#pragma unroll
    for (int k = 0; k < K4; ++k) {
        float part = w2a * rf0[k] + w2b * rf1[k] + w2ga * fg0 + w2gb * fg1;
#pragma unroll
        for (int sdown = 16; sdown > 0; sdown >>= 1)
            part += __shfl_xor_sync(FULLMASK, part, sdown);
        float wk = 1.0f / (1.0f + expf(-(part + bias2)));
        int mk = __shfl_sync(FULLMASK, kidx, k);
        float pf0 = lf[(size_t)c0 * M_ + mk];
        float pf1 = lf[(size_t)c1 * M_ + mk];
        o0 += (1.0f - wk) * rf0[k] + wk * pf0;
        o1 += (1.0f - wk) * rf1[k] + wk * pf1;
    }

    out[((size_t)b * FEAT + c0) * N_ + n] = o0;
    out[((size_t)b * FEAT + c1) * N_ + n] = o1;
}

// ---------------------------------------------------------------------------
extern "C" void kernel_launch(void* const* d_in, const int* in_sizes, int n_in,
                              void* d_out, int out_size)
{
    (void)in_sizes; (void)n_in; (void)out_size;
    const float* orig  = (const float*)d_in[0];
    const float* query = (const float*)d_in[1];
    const float* lf    = (const float*)d_in[2];
    const float* w0 = (const float*)d_in[3];
    const float* b0 = (const float*)d_in[4];
    const float* g0 = (const float*)d_in[5];
    const float* be0 = (const float*)d_in[6];
    const float* m0 = (const float*)d_in[7];
    const float* v0 = (const float*)d_in[8];
    const float* w1 = (const float*)d_in[9];
    const float* b1 = (const float*)d_in[10];
    const float* g1 = (const float*)d_in[11];
    const float* be1 = (const float*)d_in[12];
    const float* m1 = (const float*)d_in[13];
    const float* v1 = (const float*)d_in[14];
    const float* w2 = (const float*)d_in[15];
    const float* b2 = (const float*)d_in[16];
    float* out = (float*)d_out;

    dim3 g1d(N_ / P1_THREADS, B_, S_);
    knn_part_kernel<<<g1d, P1_THREADS>>>(orig, query);

    knn_merge_kernel<<<(B_ * N_) / 128, 128>>>();

    fuse_kernel<<<(B_ * N_) / S2_WARPS, S2_THREADS>>>(
        orig, query, lf,
        w0, b0, g0, be0, m0, v0,
        w1, b1, g1, be1, m1, v1,
        w2, b2, out);
}